// round 6
// baseline (speedup 1.0000x reference)
#include <cuda_runtime.h>
#include <cstddef>

#define TB    256
#define BM    64
#define DD    64
#define HH    256
#define KIN   65
#define RP    68
#define FD_EPS 1e-4f

// shared memory layout (float offsets)
#define OFF_W0   0                        // [65][256]
#define OFF_HT   (KIN*HH)                 // h transposed [256][RP]
#define OFF_INT  (OFF_HT + HH*RP)         // input transposed [65][RP]
#define OFF_W1   (OFF_INT + KIN*RP)       // double buffer [2][8][256]
#define OFF_W2   (OFF_W1 + 2*8*HH)        // double buffer [2][8][64]
#define OFF_B0   (OFF_W2 + 2*8*DD)
#define OFF_B1   (OFF_B0 + HH)
#define OFF_B2   (OFF_B1 + HH)
#define OFF_LD   (OFF_B2 + DD)
#define SMEM_FLOATS (OFF_LD + BM)         // 44228 floats = 176912 bytes

__device__ __forceinline__ void gemm_tile_k(const float* __restrict__ aptr,
                                            const float* __restrict__ bptr,
                                            float acc[64])
{
    float4 a0 = *(const float4*)(aptr);
    float4 a1 = *(const float4*)(aptr + 4);
    float4 bl = *(const float4*)(bptr);
    float4 bh = *(const float4*)(bptr + 128);
    float ar[8] = {a0.x,a0.y,a0.z,a0.w,a1.x,a1.y,a1.z,a1.w};
    float br[8] = {bl.x,bl.y,bl.z,bl.w,bh.x,bh.y,bh.z,bh.w};
#pragma unroll
    for (int i=0;i<8;i++)
#pragma unroll
        for (int j=0;j<8;j++)
            acc[i*8+j] = fmaf(ar[i], br[j], acc[i*8+j]);
}

__device__ __forceinline__ void store_h(float* s_hT, const float acc[64],
                                        const float* s_b, int tx, int ty)
{
#pragma unroll
    for (int j=0;j<8;j++){
        int c = (j<4) ? (tx*4+j) : (128 + tx*4 + (j-4));
        float b = s_b[c];
        float* dst = s_hT + c*RP + ty*8;
        float4 v0, v1;
        v0.x = fmaxf(acc[0*8+j]+b,0.f);
        v0.y = fmaxf(acc[1*8+j]+b,0.f);
        v0.z = fmaxf(acc[2*8+j]+b,0.f);
        v0.w = fmaxf(acc[3*8+j]+b,0.f);
        v1.x = fmaxf(acc[4*8+j]+b,0.f);
        v1.y = fmaxf(acc[5*8+j]+b,0.f);
        v1.z = fmaxf(acc[6*8+j]+b,0.f);
        v1.w = fmaxf(acc[7*8+j]+b,0.f);
        *(float4*)dst     = v0;
        *(float4*)(dst+4) = v1;
    }
}

__device__ __forceinline__ void write_input(float* s_inT, const float v[16],
                                            float t, int tx, int ty, int tid)
{
#pragma unroll
    for (int i=0;i<8;i++){
        s_inT[(2*tx)*RP   + ty*8+i] = v[i*2];
        s_inT[(2*tx+1)*RP + ty*8+i] = v[i*2+1];
    }
    if (tid < BM) s_inT[64*RP + tid] = t;   // time feature column
}

// One MLP eval: out = xin + relu(relu([xin,t]@W0+b0)@W1+b1)@W2 + b2
// Precondition: s_inT written + __syncthreads() done by caller.
__device__ __forceinline__ void mlp_eval(float* sm,
                                         const float* __restrict__ W1g,
                                         const float* __restrict__ W2g,
                                         const float xin[16], float outv[16],
                                         int tx, int ty)
{
    const float* s_inT = sm + OFF_INT;
    float*       s_hT  = sm + OFF_HT;
    float*       s_w1  = sm + OFF_W1;
    float*       s_w2  = sm + OFF_W2;

    float acc[64];
#pragma unroll
    for (int i=0;i<64;i++) acc[i]=0.f;

    // ---- Layer 0: [64x65] @ [65x256], W0 resident in smem ----
    {
        const float* aB = s_inT + ty*8;
        const float* bB = sm + OFF_W0 + tx*4;
#pragma unroll 5
        for (int k=0;k<KIN;k++)
            gemm_tile_k(aB + k*RP, bB + k*HH, acc);
    }
    store_h(s_hT, acc, sm + OFF_B0, tx, ty);   // h0 -> s_hT (prev readers synced)

    // ---- Layer 1 prologue: prefetch W1 tile 0 into buf0 ----
    {
        float4 p0 = *(const float4*)(W1g + (size_t)ty*HH + tx*4);
        float4 p1 = *(const float4*)(W1g + (size_t)ty*HH + 128 + tx*4);
        *(float4*)(s_w1 + ty*HH + tx*4)       = p0;
        *(float4*)(s_w1 + ty*HH + 128 + tx*4) = p1;
    }
    __syncthreads();   // h0 visible + tile0 visible

#pragma unroll
    for (int i=0;i<64;i++) acc[i]=0.f;
    {
        int p = 0;
        const float* aB = s_hT + ty*8;
#pragma unroll 1
        for (int kb=0;kb<32;kb++){
            float4 p0, p1;
            if (kb < 31){
                p0 = *(const float4*)(W1g + (size_t)((kb+1)*8+ty)*HH + tx*4);
                p1 = *(const float4*)(W1g + (size_t)((kb+1)*8+ty)*HH + 128 + tx*4);
            }
            const float* wt = s_w1 + p*(8*HH);
#pragma unroll
            for (int kk=0;kk<8;kk++)
                gemm_tile_k(aB + (kb*8+kk)*RP, wt + kk*HH + tx*4, acc);
            if (kb < 31){
                float* wd = s_w1 + (p^1)*(8*HH);
                *(float4*)(wd + ty*HH + tx*4)       = p0;
                *(float4*)(wd + ty*HH + 128 + tx*4) = p1;
            }
            __syncthreads();
            p ^= 1;
        }
    }
    store_h(s_hT, acc, sm + OFF_B1, tx, ty);   // h1 overwrites h0 (readers synced)

    // ---- Layer 2 prologue: prefetch W2 tile 0 ----
    {
        float2 q = *(const float2*)(W2g + (size_t)ty*DD + tx*2);
        *(float2*)(s_w2 + ty*DD + tx*2) = q;
    }
    __syncthreads();   // h1 visible + tile0 visible

    float acc2[16];
#pragma unroll
    for (int i=0;i<16;i++) acc2[i]=0.f;
    {
        int p = 0;
        const float* aB = s_hT + ty*8;
#pragma unroll 1
        for (int kb=0;kb<32;kb++){
            float2 q;
            if (kb < 31)
                q = *(const float2*)(W2g + (size_t)((kb+1)*8+ty)*DD + tx*2);
            const float* wt = s_w2 + p*(8*DD);
#pragma unroll
            for (int kk=0;kk<8;kk++){
                const float* ap = aB + (kb*8+kk)*RP;
                float4 a0 = *(const float4*)(ap);
                float4 a1 = *(const float4*)(ap+4);
                float2 bv = *(const float2*)(wt + kk*DD + tx*2);
                float ar[8] = {a0.x,a0.y,a0.z,a0.w,a1.x,a1.y,a1.z,a1.w};
#pragma unroll
                for (int i=0;i<8;i++){
                    acc2[i*2]   = fmaf(ar[i], bv.x, acc2[i*2]);
                    acc2[i*2+1] = fmaf(ar[i], bv.y, acc2[i*2+1]);
                }
            }
            if (kb < 31)
                *(float2*)(s_w2 + (p^1)*(8*DD) + ty*DD + tx*2) = q;
            __syncthreads();
            p ^= 1;
        }
    }
    float bx = sm[OFF_B2 + tx*2], by = sm[OFF_B2 + tx*2 + 1];
#pragma unroll
    for (int i=0;i<8;i++){
        outv[i*2]   = xin[i*2]   + acc2[i*2]   + bx;
        outv[i*2+1] = xin[i*2+1] + acc2[i*2+1] + by;
    }
}

extern "C" __global__ void __launch_bounds__(TB,1)
ffjord_kernel(const float* __restrict__ x_in, const float* __restrict__ epsg,
              const float* __restrict__ W0g, const float* __restrict__ b0g,
              const float* __restrict__ W1g, const float* __restrict__ b1g,
              const float* __restrict__ W2g, const float* __restrict__ b2g,
              float* __restrict__ outg, int rows, int nsteps)
{
    extern __shared__ float sm[];
    const int tid = threadIdx.x;
    const int tx = tid & 31, ty = tid >> 5;
    const int row0 = blockIdx.x * BM;

    // resident weights/biases
    for (int i = tid; i < KIN*HH; i += TB) sm[OFF_W0 + i] = W0g[i];
    for (int i = tid; i < HH; i += TB){ sm[OFF_B0+i] = b0g[i]; sm[OFF_B1+i] = b1g[i]; }
    if (tid < DD) sm[OFF_B2 + tid] = b2g[tid];
    if (tid < BM) sm[OFF_LD + tid] = 0.f;

    // per-thread state: rows ty*8..ty*8+7, cols 2*tx, 2*tx+1
    float xc[16];
#pragma unroll
    for (int i=0;i<8;i++){
        float2 v = *(const float2*)(x_in + (size_t)(row0 + ty*8 + i)*DD + tx*2);
        xc[i*2] = v.x; xc[i*2+1] = v.y;
    }

    const float dt = 1.0f / (float)nsteps;
    const float inv_eps = 1.0f / FD_EPS;

    for (int step=0; step<nsteps; step++){
        float t = step * dt;
        float e[16];
#pragma unroll
        for (int i=0;i<8;i++){
            float2 v = *(const float2*)(epsg + ((size_t)step*rows + row0 + ty*8 + i)*DD + tx*2);
            e[i*2] = v.x; e[i*2+1] = v.y;
        }
        float k1[16], kv[16], rk[16], tmp[16];

        // base eval (= RK4 k1)
        write_input(sm + OFF_INT, xc, t, tx, ty, tid);
        __syncthreads();
        mlp_eval(sm, W1g, W2g, xc, k1, tx, ty);

        // plus eval for FD trace
#pragma unroll
        for (int i=0;i<16;i++) tmp[i] = xc[i] + 0.5f*FD_EPS*e[i];
        write_input(sm + OFF_INT, tmp, t, tx, ty, tid);
        __syncthreads();
        mlp_eval(sm, W1g, W2g, tmp, kv, tx, ty);

        // trace = sum_c e * (plus-base)/eps ; warp (tx) butterfly per row
#pragma unroll
        for (int i=0;i<8;i++){
            float pi = e[i*2]*(kv[i*2]-k1[i*2]) + e[i*2+1]*(kv[i*2+1]-k1[i*2+1]);
#pragma unroll
            for (int off=16; off; off>>=1) pi += __shfl_xor_sync(0xffffffffu, pi, off);
            if (tx == 0) sm[OFF_LD + ty*8 + i] -= pi * inv_eps * dt;
        }

        // k2
#pragma unroll
        for (int i=0;i<16;i++){ rk[i] = k1[i]; tmp[i] = xc[i] + 0.5f*dt*k1[i]; }
        write_input(sm + OFF_INT, tmp, t + 0.5f*dt, tx, ty, tid);
        __syncthreads();
        mlp_eval(sm, W1g, W2g, tmp, kv, tx, ty);
        // k3
#pragma unroll
        for (int i=0;i<16;i++){ rk[i] += 2.f*kv[i]; tmp[i] = xc[i] + 0.5f*dt*kv[i]; }
        write_input(sm + OFF_INT, tmp, t + 0.5f*dt, tx, ty, tid);
        __syncthreads();
        mlp_eval(sm, W1g, W2g, tmp, kv, tx, ty);
        // k4
#pragma unroll
        for (int i=0;i<16;i++){ rk[i] += 2.f*kv[i]; tmp[i] = xc[i] + dt*kv[i]; }
        write_input(sm + OFF_INT, tmp, t + dt, tx, ty, tid);
        __syncthreads();
        mlp_eval(sm, W1g, W2g, tmp, kv, tx, ty);
        // x update
#pragma unroll
        for (int i=0;i<16;i++){ rk[i] += kv[i]; xc[i] += (dt*(1.0f/6.0f))*rk[i]; }
    }

    // outputs: x_out [rows*64] then log_det [rows]
#pragma unroll
    for (int i=0;i<8;i++){
        float2 v; v.x = xc[i*2]; v.y = xc[i*2+1];
        *(float2*)(outg + (size_t)(row0 + ty*8 + i)*DD + tx*2) = v;
    }
    __syncthreads();
    if (tid < BM) outg[(size_t)rows*DD + row0 + tid] = sm[OFF_LD + tid];
}

extern "C" void kernel_launch(void* const* d_in, const int* in_sizes, int n_in,
                              void* d_out, int out_size)
{
    const float* x   = (const float*)d_in[0];
    const float* eps = (const float*)d_in[1];
    const float* W0  = (const float*)d_in[2];
    const float* b0  = (const float*)d_in[3];
    const float* W1  = (const float*)d_in[4];
    const float* b1  = (const float*)d_in[5];
    const float* W2  = (const float*)d_in[6];
    const float* b2  = (const float*)d_in[7];
    float* out = (float*)d_out;

    int rows   = in_sizes[0] / DD;                 // 65536
    int nsteps = in_sizes[1] / in_sizes[0];        // 16

    size_t smem_bytes = (size_t)SMEM_FLOATS * sizeof(float);   // 176912
    cudaFuncSetAttribute(ffjord_kernel,
                         cudaFuncAttributeMaxDynamicSharedMemorySize,
                         (int)smem_bytes);

    dim3 grid(rows / BM), block(TB);
    ffjord_kernel<<<grid, block, smem_bytes>>>(x, eps, W0, b0, W1, b1, W2, b2,
                                               out, rows, nsteps);
}

// round 7
// speedup vs baseline: 1.0007x; 1.0007x over previous
#include <cuda_runtime.h>
#include <cstddef>

#define TB    256
#define BM    64
#define DD    64
#define HH    256
#define KIN   65
#define RP    68
#define FD_EPS 1e-4f

// shared memory layout (float offsets)
#define OFF_W0   0                        // [65][256]
#define OFF_HT   (KIN*HH)                 // h transposed [256][RP]
#define OFF_INT  (OFF_HT + HH*RP)         // input transposed [65][RP]
#define OFF_W1   (OFF_INT + KIN*RP)       // double buffer [2][8][256]
#define OFF_W2   (OFF_W1 + 2*8*HH)        // double buffer [2][8][64]
#define OFF_B0   (OFF_W2 + 2*8*DD)
#define OFF_B1   (OFF_B0 + HH)
#define OFF_B2   (OFF_B1 + HH)
#define OFF_LD   (OFF_B2 + DD)
#define SMEM_FLOATS (OFF_LD + BM)         // 44228 floats = 176912 bytes

__device__ __forceinline__ void gemm_tile_k(const float* __restrict__ aptr,
                                            const float* __restrict__ bptr,
                                            float acc[64])
{
    float4 a0 = *(const float4*)(aptr);
    float4 a1 = *(const float4*)(aptr + 4);
    float4 bl = *(const float4*)(bptr);
    float4 bh = *(const float4*)(bptr + 128);
    float ar[8] = {a0.x,a0.y,a0.z,a0.w,a1.x,a1.y,a1.z,a1.w};
    float br[8] = {bl.x,bl.y,bl.z,bl.w,bh.x,bh.y,bh.z,bh.w};
#pragma unroll
    for (int i=0;i<8;i++)
#pragma unroll
        for (int j=0;j<8;j++)
            acc[i*8+j] = fmaf(ar[i], br[j], acc[i*8+j]);
}

__device__ __forceinline__ void store_h(float* s_hT, const float acc[64],
                                        const float* s_b, int tx, int ty)
{
#pragma unroll
    for (int j=0;j<8;j++){
        int c = (j<4) ? (tx*4+j) : (128 + tx*4 + (j-4));
        float b = s_b[c];
        float* dst = s_hT + c*RP + ty*8;
        float4 v0, v1;
        v0.x = fmaxf(acc[0*8+j]+b,0.f);
        v0.y = fmaxf(acc[1*8+j]+b,0.f);
        v0.z = fmaxf(acc[2*8+j]+b,0.f);
        v0.w = fmaxf(acc[3*8+j]+b,0.f);
        v1.x = fmaxf(acc[4*8+j]+b,0.f);
        v1.y = fmaxf(acc[5*8+j]+b,0.f);
        v1.z = fmaxf(acc[6*8+j]+b,0.f);
        v1.w = fmaxf(acc[7*8+j]+b,0.f);
        *(float4*)dst     = v0;
        *(float4*)(dst+4) = v1;
    }
}

__device__ __forceinline__ void write_input(float* s_inT, const float v[16],
                                            float t, int tx, int ty, int tid)
{
#pragma unroll
    for (int i=0;i<8;i++){
        s_inT[(2*tx)*RP   + ty*8+i] = v[i*2];
        s_inT[(2*tx+1)*RP + ty*8+i] = v[i*2+1];
    }
    if (tid < BM) s_inT[64*RP + tid] = t;   // time feature column
}

// One MLP eval: out = xin + relu(relu([xin,t]@W0+b0)@W1+b1)@W2 + b2
// Precondition: s_inT written + __syncthreads() done by caller.
__device__ __forceinline__ void mlp_eval(float* sm,
                                         const float* __restrict__ W1g,
                                         const float* __restrict__ W2g,
                                         const float xin[16], float outv[16],
                                         int tx, int ty)
{
    const float* s_inT = sm + OFF_INT;
    float*       s_hT  = sm + OFF_HT;
    float*       s_w1  = sm + OFF_W1;
    float*       s_w2  = sm + OFF_W2;

    float acc[64];
#pragma unroll
    for (int i=0;i<64;i++) acc[i]=0.f;

    // ---- Layer 0: [64x65] @ [65x256], W0 resident in smem ----
    {
        const float* aB = s_inT + ty*8;
        const float* bB = sm + OFF_W0 + tx*4;
#pragma unroll 5
        for (int k=0;k<KIN;k++)
            gemm_tile_k(aB + k*RP, bB + k*HH, acc);
    }
    store_h(s_hT, acc, sm + OFF_B0, tx, ty);   // h0 -> s_hT (prev readers synced)

    // ---- Layer 1 prologue: prefetch W1 tile 0 into buf0 ----
    {
        float4 p0 = *(const float4*)(W1g + (size_t)ty*HH + tx*4);
        float4 p1 = *(const float4*)(W1g + (size_t)ty*HH + 128 + tx*4);
        *(float4*)(s_w1 + ty*HH + tx*4)       = p0;
        *(float4*)(s_w1 + ty*HH + 128 + tx*4) = p1;
    }
    __syncthreads();   // h0 visible + tile0 visible

#pragma unroll
    for (int i=0;i<64;i++) acc[i]=0.f;
    {
        int p = 0;
        const float* aB = s_hT + ty*8;
#pragma unroll 1
        for (int kb=0;kb<32;kb++){
            float4 p0, p1;
            if (kb < 31){
                p0 = *(const float4*)(W1g + (size_t)((kb+1)*8+ty)*HH + tx*4);
                p1 = *(const float4*)(W1g + (size_t)((kb+1)*8+ty)*HH + 128 + tx*4);
            }
            const float* wt = s_w1 + p*(8*HH);
#pragma unroll
            for (int kk=0;kk<8;kk++)
                gemm_tile_k(aB + (kb*8+kk)*RP, wt + kk*HH + tx*4, acc);
            if (kb < 31){
                float* wd = s_w1 + (p^1)*(8*HH);
                *(float4*)(wd + ty*HH + tx*4)       = p0;
                *(float4*)(wd + ty*HH + 128 + tx*4) = p1;
            }
            __syncthreads();
            p ^= 1;
        }
    }
    store_h(s_hT, acc, sm + OFF_B1, tx, ty);   // h1 overwrites h0 (readers synced)

    // ---- Layer 2 prologue: prefetch W2 tile 0 ----
    {
        float2 q = *(const float2*)(W2g + (size_t)ty*DD + tx*2);
        *(float2*)(s_w2 + ty*DD + tx*2) = q;
    }
    __syncthreads();   // h1 visible + tile0 visible

    float acc2[16];
#pragma unroll
    for (int i=0;i<16;i++) acc2[i]=0.f;
    {
        int p = 0;
        const float* aB = s_hT + ty*8;
#pragma unroll 1
        for (int kb=0;kb<32;kb++){
            float2 q;
            if (kb < 31)
                q = *(const float2*)(W2g + (size_t)((kb+1)*8+ty)*DD + tx*2);
            const float* wt = s_w2 + p*(8*DD);
#pragma unroll
            for (int kk=0;kk<8;kk++){
                const float* ap = aB + (kb*8+kk)*RP;
                float4 a0 = *(const float4*)(ap);
                float4 a1 = *(const float4*)(ap+4);
                float2 bv = *(const float2*)(wt + kk*DD + tx*2);
                float ar[8] = {a0.x,a0.y,a0.z,a0.w,a1.x,a1.y,a1.z,a1.w};
#pragma unroll
                for (int i=0;i<8;i++){
                    acc2[i*2]   = fmaf(ar[i], bv.x, acc2[i*2]);
                    acc2[i*2+1] = fmaf(ar[i], bv.y, acc2[i*2+1]);
                }
            }
            if (kb < 31)
                *(float2*)(s_w2 + (p^1)*(8*DD) + ty*DD + tx*2) = q;
            __syncthreads();
            p ^= 1;
        }
    }
    float bx = sm[OFF_B2 + tx*2], by = sm[OFF_B2 + tx*2 + 1];
#pragma unroll
    for (int i=0;i<8;i++){
        outv[i*2]   = xin[i*2]   + acc2[i*2]   + bx;
        outv[i*2+1] = xin[i*2+1] + acc2[i*2+1] + by;
    }
}

extern "C" __global__ void __launch_bounds__(TB,1)
ffjord_kernel(const float* __restrict__ x_in, const float* __restrict__ epsg,
              const float* __restrict__ W0g, const float* __restrict__ b0g,
              const float* __restrict__ W1g, const float* __restrict__ b1g,
              const float* __restrict__ W2g, const float* __restrict__ b2g,
              float* __restrict__ outg, int rows, int nsteps)
{
    extern __shared__ float sm[];
    const int tid = threadIdx.x;
    const int tx = tid & 31, ty = tid >> 5;
    const int row0 = blockIdx.x * BM;

    // resident weights/biases
    for (int i = tid; i < KIN*HH; i += TB) sm[OFF_W0 + i] = W0g[i];
    for (int i = tid; i < HH; i += TB){ sm[OFF_B0+i] = b0g[i]; sm[OFF_B1+i] = b1g[i]; }
    if (tid < DD) sm[OFF_B2 + tid] = b2g[tid];
    if (tid < BM) sm[OFF_LD + tid] = 0.f;

    // per-thread state: rows ty*8..ty*8+7, cols 2*tx, 2*tx+1
    float xc[16];
#pragma unroll
    for (int i=0;i<8;i++){
        float2 v = *(const float2*)(x_in + (size_t)(row0 + ty*8 + i)*DD + tx*2);
        xc[i*2] = v.x; xc[i*2+1] = v.y;
    }

    const float dt = 1.0f / (float)nsteps;
    const float inv_eps = 1.0f / FD_EPS;

    for (int step=0; step<nsteps; step++){
        float t = step * dt;
        float e[16];
#pragma unroll
        for (int i=0;i<8;i++){
            float2 v = *(const float2*)(epsg + ((size_t)step*rows + row0 + ty*8 + i)*DD + tx*2);
            e[i*2] = v.x; e[i*2+1] = v.y;
        }
        float k1[16], kv[16], rk[16], tmp[16];

        // base eval (= RK4 k1)
        write_input(sm + OFF_INT, xc, t, tx, ty, tid);
        __syncthreads();
        mlp_eval(sm, W1g, W2g, xc, k1, tx, ty);

        // plus eval for FD trace
#pragma unroll
        for (int i=0;i<16;i++) tmp[i] = xc[i] + 0.5f*FD_EPS*e[i];
        write_input(sm + OFF_INT, tmp, t, tx, ty, tid);
        __syncthreads();
        mlp_eval(sm, W1g, W2g, tmp, kv, tx, ty);

        // trace = sum_c e * (plus-base)/eps ; warp (tx) butterfly per row
#pragma unroll
        for (int i=0;i<8;i++){
            float pi = e[i*2]*(kv[i*2]-k1[i*2]) + e[i*2+1]*(kv[i*2+1]-k1[i*2+1]);
#pragma unroll
            for (int off=16; off; off>>=1) pi += __shfl_xor_sync(0xffffffffu, pi, off);
            if (tx == 0) sm[OFF_LD + ty*8 + i] -= pi * inv_eps * dt;
        }

        // k2
#pragma unroll
        for (int i=0;i<16;i++){ rk[i] = k1[i]; tmp[i] = xc[i] + 0.5f*dt*k1[i]; }
        write_input(sm + OFF_INT, tmp, t + 0.5f*dt, tx, ty, tid);
        __syncthreads();
        mlp_eval(sm, W1g, W2g, tmp, kv, tx, ty);
        // k3
#pragma unroll
        for (int i=0;i<16;i++){ rk[i] += 2.f*kv[i]; tmp[i] = xc[i] + 0.5f*dt*kv[i]; }
        write_input(sm + OFF_INT, tmp, t + 0.5f*dt, tx, ty, tid);
        __syncthreads();
        mlp_eval(sm, W1g, W2g, tmp, kv, tx, ty);
        // k4
#pragma unroll
        for (int i=0;i<16;i++){ rk[i] += 2.f*kv[i]; tmp[i] = xc[i] + dt*kv[i]; }
        write_input(sm + OFF_INT, tmp, t + dt, tx, ty, tid);
        __syncthreads();
        mlp_eval(sm, W1g, W2g, tmp, kv, tx, ty);
        // x update
#pragma unroll
        for (int i=0;i<16;i++){ rk[i] += kv[i]; xc[i] += (dt*(1.0f/6.0f))*rk[i]; }
    }

    // outputs: x_out [rows*64] then log_det [rows]
#pragma unroll
    for (int i=0;i<8;i++){
        float2 v; v.x = xc[i*2]; v.y = xc[i*2+1];
        *(float2*)(outg + (size_t)(row0 + ty*8 + i)*DD + tx*2) = v;
    }
    __syncthreads();
    if (tid < BM) outg[(size_t)rows*DD + row0 + tid] = sm[OFF_LD + tid];
}

extern "C" void kernel_launch(void* const* d_in, const int* in_sizes, int n_in,
                              void* d_out, int out_size)
{
    const float* x   = (const float*)d_in[0];
    const float* eps = (const float*)d_in[1];
    const float* W0  = (const float*)d_in[2];
    const float* b0  = (const float*)d_in[3];
    const float* W1  = (const float*)d_in[4];
    const float* b1  = (const float*)d_in[5];
    const float* W2  = (const float*)d_in[6];
    const float* b2  = (const float*)d_in[7];
    float* out = (float*)d_out;

    int rows   = in_sizes[0] / DD;                 // 65536
    int nsteps = in_sizes[1] / in_sizes[0];        // 16

    size_t smem_bytes = (size_t)SMEM_FLOATS * sizeof(float);   // 176912
    cudaFuncSetAttribute(ffjord_kernel,
                         cudaFuncAttributeMaxDynamicSharedMemorySize,
                         (int)smem_bytes);

    dim3 grid(rows / BM), block(TB);
    ffjord_kernel<<<grid, block, smem_bytes>>>(x, eps, W0, b0, W1, b1, W2, b2,
                                               out, rows, nsteps);
}

// round 8
// speedup vs baseline: 1.0011x; 1.0004x over previous
#include <cuda_runtime.h>
#include <cstddef>

#define TB    256
#define BM    64
#define DD    64
#define HH    256
#define KIN   65
#define RP    68
#define FD_EPS 1e-4f

// shared memory layout (float offsets)
#define OFF_W0   0                        // [65][256]
#define OFF_HT   (KIN*HH)                 // h transposed [256][RP]
#define OFF_INT  (OFF_HT + HH*RP)         // input transposed [65][RP]
#define OFF_W1   (OFF_INT + KIN*RP)       // double buffer [2][8][256]
#define OFF_W2   (OFF_W1 + 2*8*HH)        // double buffer [2][8][64]
#define OFF_B0   (OFF_W2 + 2*8*DD)
#define OFF_B1   (OFF_B0 + HH)
#define OFF_B2   (OFF_B1 + HH)
#define OFF_LD   (OFF_B2 + DD)
#define SMEM_FLOATS (OFF_LD + BM)         // 44228 floats = 176912 bytes

__device__ __forceinline__ void gemm_tile_k(const float* __restrict__ aptr,
                                            const float* __restrict__ bptr,
                                            float acc[64])
{
    float4 a0 = *(const float4*)(aptr);
    float4 a1 = *(const float4*)(aptr + 4);
    float4 bl = *(const float4*)(bptr);
    float4 bh = *(const float4*)(bptr + 128);
    float ar[8] = {a0.x,a0.y,a0.z,a0.w,a1.x,a1.y,a1.z,a1.w};
    float br[8] = {bl.x,bl.y,bl.z,bl.w,bh.x,bh.y,bh.z,bh.w};
#pragma unroll
    for (int i=0;i<8;i++)
#pragma unroll
        for (int j=0;j<8;j++)
            acc[i*8+j] = fmaf(ar[i], br[j], acc[i*8+j]);
}

__device__ __forceinline__ void store_h(float* s_hT, const float acc[64],
                                        const float* s_b, int tx, int ty)
{
#pragma unroll
    for (int j=0;j<8;j++){
        int c = (j<4) ? (tx*4+j) : (128 + tx*4 + (j-4));
        float b = s_b[c];
        float* dst = s_hT + c*RP + ty*8;
        float4 v0, v1;
        v0.x = fmaxf(acc[0*8+j]+b,0.f);
        v0.y = fmaxf(acc[1*8+j]+b,0.f);
        v0.z = fmaxf(acc[2*8+j]+b,0.f);
        v0.w = fmaxf(acc[3*8+j]+b,0.f);
        v1.x = fmaxf(acc[4*8+j]+b,0.f);
        v1.y = fmaxf(acc[5*8+j]+b,0.f);
        v1.z = fmaxf(acc[6*8+j]+b,0.f);
        v1.w = fmaxf(acc[7*8+j]+b,0.f);
        *(float4*)dst     = v0;
        *(float4*)(dst+4) = v1;
    }
}

__device__ __forceinline__ void write_input(float* s_inT, const float v[16],
                                            float t, int tx, int ty, int tid)
{
#pragma unroll
    for (int i=0;i<8;i++){
        s_inT[(2*tx)*RP   + ty*8+i] = v[i*2];
        s_inT[(2*tx+1)*RP + ty*8+i] = v[i*2+1];
    }
    if (tid < BM) s_inT[64*RP + tid] = t;   // time feature column
}

// One MLP eval: out = xin + relu(relu([xin,t]@W0+b0)@W1+b1)@W2 + b2
// Precondition: s_inT written + __syncthreads() done by caller.
__device__ __forceinline__ void mlp_eval(float* sm,
                                         const float* __restrict__ W1g,
                                         const float* __restrict__ W2g,
                                         const float xin[16], float outv[16],
                                         int tx, int ty)
{
    const float* s_inT = sm + OFF_INT;
    float*       s_hT  = sm + OFF_HT;
    float*       s_w1  = sm + OFF_W1;
    float*       s_w2  = sm + OFF_W2;

    float acc[64];
#pragma unroll
    for (int i=0;i<64;i++) acc[i]=0.f;

    // ---- Layer 0: [64x65] @ [65x256], W0 resident in smem ----
    {
        const float* aB = s_inT + ty*8;
        const float* bB = sm + OFF_W0 + tx*4;
#pragma unroll 5
        for (int k=0;k<KIN;k++)
            gemm_tile_k(aB + k*RP, bB + k*HH, acc);
    }
    store_h(s_hT, acc, sm + OFF_B0, tx, ty);   // h0 -> s_hT (prev readers synced)

    // ---- Layer 1 prologue: prefetch W1 tile 0 into buf0 ----
    {
        float4 p0 = *(const float4*)(W1g + (size_t)ty*HH + tx*4);
        float4 p1 = *(const float4*)(W1g + (size_t)ty*HH + 128 + tx*4);
        *(float4*)(s_w1 + ty*HH + tx*4)       = p0;
        *(float4*)(s_w1 + ty*HH + 128 + tx*4) = p1;
    }
    __syncthreads();   // h0 visible + tile0 visible

#pragma unroll
    for (int i=0;i<64;i++) acc[i]=0.f;
    {
        int p = 0;
        const float* aB = s_hT + ty*8;
#pragma unroll 1
        for (int kb=0;kb<32;kb++){
            float4 p0, p1;
            if (kb < 31){
                p0 = *(const float4*)(W1g + (size_t)((kb+1)*8+ty)*HH + tx*4);
                p1 = *(const float4*)(W1g + (size_t)((kb+1)*8+ty)*HH + 128 + tx*4);
            }
            const float* wt = s_w1 + p*(8*HH);
#pragma unroll
            for (int kk=0;kk<8;kk++)
                gemm_tile_k(aB + (kb*8+kk)*RP, wt + kk*HH + tx*4, acc);
            if (kb < 31){
                float* wd = s_w1 + (p^1)*(8*HH);
                *(float4*)(wd + ty*HH + tx*4)       = p0;
                *(float4*)(wd + ty*HH + 128 + tx*4) = p1;
            }
            __syncthreads();
            p ^= 1;
        }
    }
    store_h(s_hT, acc, sm + OFF_B1, tx, ty);   // h1 overwrites h0 (readers synced)

    // ---- Layer 2 prologue: prefetch W2 tile 0 ----
    {
        float2 q = *(const float2*)(W2g + (size_t)ty*DD + tx*2);
        *(float2*)(s_w2 + ty*DD + tx*2) = q;
    }
    __syncthreads();   // h1 visible + tile0 visible

    float acc2[16];
#pragma unroll
    for (int i=0;i<16;i++) acc2[i]=0.f;
    {
        int p = 0;
        const float* aB = s_hT + ty*8;
#pragma unroll 1
        for (int kb=0;kb<32;kb++){
            float2 q;
            if (kb < 31)
                q = *(const float2*)(W2g + (size_t)((kb+1)*8+ty)*DD + tx*2);
            const float* wt = s_w2 + p*(8*DD);
#pragma unroll
            for (int kk=0;kk<8;kk++){
                const float* ap = aB + (kb*8+kk)*RP;
                float4 a0 = *(const float4*)(ap);
                float4 a1 = *(const float4*)(ap+4);
                float2 bv = *(const float2*)(wt + kk*DD + tx*2);
                float ar[8] = {a0.x,a0.y,a0.z,a0.w,a1.x,a1.y,a1.z,a1.w};
#pragma unroll
                for (int i=0;i<8;i++){
                    acc2[i*2]   = fmaf(ar[i], bv.x, acc2[i*2]);
                    acc2[i*2+1] = fmaf(ar[i], bv.y, acc2[i*2+1]);
                }
            }
            if (kb < 31)
                *(float2*)(s_w2 + (p^1)*(8*DD) + ty*DD + tx*2) = q;
            __syncthreads();
            p ^= 1;
        }
    }
    float bx = sm[OFF_B2 + tx*2], by = sm[OFF_B2 + tx*2 + 1];
#pragma unroll
    for (int i=0;i<8;i++){
        outv[i*2]   = xin[i*2]   + acc2[i*2]   + bx;
        outv[i*2+1] = xin[i*2+1] + acc2[i*2+1] + by;
    }
}

extern "C" __global__ void __launch_bounds__(TB,1)
ffjord_kernel(const float* __restrict__ x_in, const float* __restrict__ epsg,
              const float* __restrict__ W0g, const float* __restrict__ b0g,
              const float* __restrict__ W1g, const float* __restrict__ b1g,
              const float* __restrict__ W2g, const float* __restrict__ b2g,
              float* __restrict__ outg, int rows, int nsteps)
{
    extern __shared__ float sm[];
    const int tid = threadIdx.x;
    const int tx = tid & 31, ty = tid >> 5;
    const int row0 = blockIdx.x * BM;

    // resident weights/biases
    for (int i = tid; i < KIN*HH; i += TB) sm[OFF_W0 + i] = W0g[i];
    for (int i = tid; i < HH; i += TB){ sm[OFF_B0+i] = b0g[i]; sm[OFF_B1+i] = b1g[i]; }
    if (tid < DD) sm[OFF_B2 + tid] = b2g[tid];
    if (tid < BM) sm[OFF_LD + tid] = 0.f;

    // per-thread state: rows ty*8..ty*8+7, cols 2*tx, 2*tx+1
    float xc[16];
#pragma unroll
    for (int i=0;i<8;i++){
        float2 v = *(const float2*)(x_in + (size_t)(row0 + ty*8 + i)*DD + tx*2);
        xc[i*2] = v.x; xc[i*2+1] = v.y;
    }

    const float dt = 1.0f / (float)nsteps;
    const float inv_eps = 1.0f / FD_EPS;

    for (int step=0; step<nsteps; step++){
        float t = step * dt;
        float e[16];
#pragma unroll
        for (int i=0;i<8;i++){
            float2 v = *(const float2*)(epsg + ((size_t)step*rows + row0 + ty*8 + i)*DD + tx*2);
            e[i*2] = v.x; e[i*2+1] = v.y;
        }
        float k1[16], kv[16], rk[16], tmp[16];

        // base eval (= RK4 k1)
        write_input(sm + OFF_INT, xc, t, tx, ty, tid);
        __syncthreads();
        mlp_eval(sm, W1g, W2g, xc, k1, tx, ty);

        // plus eval for FD trace
#pragma unroll
        for (int i=0;i<16;i++) tmp[i] = xc[i] + 0.5f*FD_EPS*e[i];
        write_input(sm + OFF_INT, tmp, t, tx, ty, tid);
        __syncthreads();
        mlp_eval(sm, W1g, W2g, tmp, kv, tx, ty);

        // trace = sum_c e * (plus-base)/eps ; warp (tx) butterfly per row
#pragma unroll
        for (int i=0;i<8;i++){
            float pi = e[i*2]*(kv[i*2]-k1[i*2]) + e[i*2+1]*(kv[i*2+1]-k1[i*2+1]);
#pragma unroll
            for (int off=16; off; off>>=1) pi += __shfl_xor_sync(0xffffffffu, pi, off);
            if (tx == 0) sm[OFF_LD + ty*8 + i] -= pi * inv_eps * dt;
        }

        // k2
#pragma unroll
        for (int i=0;i<16;i++){ rk[i] = k1[i]; tmp[i] = xc[i] + 0.5f*dt*k1[i]; }
        write_input(sm + OFF_INT, tmp, t + 0.5f*dt, tx, ty, tid);
        __syncthreads();
        mlp_eval(sm, W1g, W2g, tmp, kv, tx, ty);
        // k3
#pragma unroll
        for (int i=0;i<16;i++){ rk[i] += 2.f*kv[i]; tmp[i] = xc[i] + 0.5f*dt*kv[i]; }
        write_input(sm + OFF_INT, tmp, t + 0.5f*dt, tx, ty, tid);
        __syncthreads();
        mlp_eval(sm, W1g, W2g, tmp, kv, tx, ty);
        // k4
#pragma unroll
        for (int i=0;i<16;i++){ rk[i] += 2.f*kv[i]; tmp[i] = xc[i] + dt*kv[i]; }
        write_input(sm + OFF_INT, tmp, t + dt, tx, ty, tid);
        __syncthreads();
        mlp_eval(sm, W1g, W2g, tmp, kv, tx, ty);
        // x update
#pragma unroll
        for (int i=0;i<16;i++){ rk[i] += kv[i]; xc[i] += (dt*(1.0f/6.0f))*rk[i]; }
    }

    // outputs: x_out [rows*64] then log_det [rows]
#pragma unroll
    for (int i=0;i<8;i++){
        float2 v; v.x = xc[i*2]; v.y = xc[i*2+1];
        *(float2*)(outg + (size_t)(row0 + ty*8 + i)*DD + tx*2) = v;
    }
    __syncthreads();
    if (tid < BM) outg[(size_t)rows*DD + row0 + tid] = sm[OFF_LD + tid];
}

extern "C" void kernel_launch(void* const* d_in, const int* in_sizes, int n_in,
                              void* d_out, int out_size)
{
    const float* x   = (const float*)d_in[0];
    const float* eps = (const float*)d_in[1];
    const float* W0  = (const float*)d_in[2];
    const float* b0  = (const float*)d_in[3];
    const float* W1  = (const float*)d_in[4];
    const float* b1  = (const float*)d_in[5];
    const float* W2  = (const float*)d_in[6];
    const float* b2  = (const float*)d_in[7];
    float* out = (float*)d_out;

    int rows   = in_sizes[0] / DD;                 // 65536
    int nsteps = in_sizes[1] / in_sizes[0];        // 16

    size_t smem_bytes = (size_t)SMEM_FLOATS * sizeof(float);   // 176912
    cudaFuncSetAttribute(ffjord_kernel,
                         cudaFuncAttributeMaxDynamicSharedMemorySize,
                         (int)smem_bytes);

    dim3 grid(rows / BM), block(TB);
    ffjord_kernel<<<grid, block, smem_bytes>>>(x, eps, W0, b0, W1, b1, W2, b2,
                                               out, rows, nsteps);
}